// round 15
// baseline (speedup 1.0000x reference)
#include <cuda_runtime.h>
#include <cuda_bf16.h>
#include <math.h>
#include <stdint.h>

// ---------------- problem constants ----------------
#define BATCH   8
#define SEQ     1024
#define M_ROWS  (BATCH*SEQ)        // 8192
#define D_MODEL 256
#define D_INNER 512
#define D_STATE 16
#define DT_RANK 16
#define N_LAYERS 4
#define W2V_DIM 768
#define LIB_DIM 93
#define NCH     16                 // scan chunks
#define CH      (SEQ/NCH)          // 64

// ---------------- scratch buffers ----------------
__device__ float g_wl [M_ROWS * (2*D_MODEL)];
__device__ float g_t  [M_ROWS * D_MODEL];
__device__ float g_h  [M_ROWS * D_MODEL];
__device__ float g_xln[M_ROWS * D_MODEL];
__device__ float g_xz [M_ROWS * (2*D_INNER)];
__device__ float g_xc [M_ROWS * D_INNER];
__device__ float g_dbl[M_ROWS * (DT_RANK+2*D_STATE)];
__device__ float g_dt [M_ROWS * D_INNER];
__device__ float g_y  [M_ROWS * D_INNER];

// ============================================================
// bf16-split tensor-core GEMM (R12 winner: BK=32 + XOR swizzle)
// ============================================================
#define GBM 128
#define GBN 64
#define GBK 32
#define GROW 32

#define SA_SZ (GBM*GROW)
#define SW_SZ (GBN*GROW)
#define SMEM_WORDS (2*SA_SZ + 2*SW_SZ)   // 48KB

#define NQA 4
#define NQW 2

__device__ __forceinline__ void mma_bf16(float c[4], uint32_t a0, uint32_t a1,
                                         uint32_t a2, uint32_t a3,
                                         uint32_t b0, uint32_t b1) {
    asm volatile(
        "mma.sync.aligned.m16n8k16.row.col.f32.bf16.bf16.f32 "
        "{%0,%1,%2,%3}, {%4,%5,%6,%7}, {%8,%9}, {%0,%1,%2,%3};"
        : "+f"(c[0]), "+f"(c[1]), "+f"(c[2]), "+f"(c[3])
        : "r"(a0), "r"(a1), "r"(a2), "r"(a3), "r"(b0), "r"(b1));
}

__device__ __forceinline__ uint32_t pack_bf(float v0, float v1) {
    __nv_bfloat162 p = __halves2bfloat162(__float2bfloat16_rn(v0),
                                          __float2bfloat16_rn(v1));
    return *(uint32_t*)&p;
}

__device__ __forceinline__ uint4 make_quad(float v0, float v1, float v2, float v3) {
    float h0 = __bfloat162float(__float2bfloat16_rn(v0));
    float h1 = __bfloat162float(__float2bfloat16_rn(v1));
    float h2 = __bfloat162float(__float2bfloat16_rn(v2));
    float h3 = __bfloat162float(__float2bfloat16_rn(v3));
    uint4 q;
    q.x = pack_bf(v0, v1);
    q.y = pack_bf(v2, v3);
    q.z = pack_bf(v0 - h0, v1 - h1);
    q.w = pack_bf(v2 - h2, v3 - h3);
    return q;
}

__device__ __forceinline__ int quad_off(int row, int ks, int tg) {
    return row * GROW + (((ks << 4) + (tg << 2)) ^ ((row & 1) << 4));
}

template<bool ACC>
__global__ __launch_bounds__(256, 2)
void gemm_bf16(const float* __restrict__ A, const float* __restrict__ W,
               const float* __restrict__ bias, float* __restrict__ C,
               int M, int N, int K, int ldc)
{
    extern __shared__ uint32_t smem[];
    uint32_t* As = smem;
    uint32_t* Ws = smem + 2 * SA_SZ;

    const int tid  = threadIdx.x;
    const int lane = tid & 31;
    const int g    = lane >> 2;
    const int tg   = lane & 3;
    const int warp = tid >> 5;
    const int wm   = warp >> 2;
    const int wn   = warp & 3;
    const int m0   = blockIdx.y * GBM;
    const int n0   = blockIdx.x * GBN;

    float acc[4][2][4];
#pragma unroll
    for (int i = 0; i < 4; i++)
#pragma unroll
        for (int j = 0; j < 2; j++)
#pragma unroll
            for (int l = 0; l < 4; l++) acc[i][j][l] = 0.f;

    const int ntiles = (K + GBK - 1) / GBK;

    int qrA[NQA], qkA[NQA], qtA[NQA], qoA[NQA];
    int qrW[NQW], qkW[NQW], qtW[NQW], qoW[NQW];
#pragma unroll
    for (int i = 0; i < NQA; i++) {
        int q = tid + i * 256;
        qrA[i] = q >> 3; qkA[i] = (q >> 2) & 1; qtA[i] = q & 3;
        qoA[i] = quad_off(qrA[i], qkA[i], qtA[i]);
    }
#pragma unroll
    for (int i = 0; i < NQW; i++) {
        int q = tid + i * 256;
        qrW[i] = q >> 3; qkW[i] = (q >> 2) & 1; qtW[i] = q & 3;
        qoW[i] = quad_off(qrW[i], qkW[i], qtW[i]);
    }

    float vA[NQA][4], vW[NQW][4];

    auto loadg = [&](int kt) {
#pragma unroll
        for (int i = 0; i < NQA; i++) {
            int kbase = kt * GBK + qkA[i] * 16 + 2 * qtA[i];
            const float* p = A + (size_t)(m0 + qrA[i]) * K + kbase;
            vA[i][0] = (kbase     < K) ? p[0] : 0.f;
            vA[i][1] = (kbase + 1 < K) ? p[1] : 0.f;
            vA[i][2] = (kbase + 8 < K) ? p[8] : 0.f;
            vA[i][3] = (kbase + 9 < K) ? p[9] : 0.f;
        }
#pragma unroll
        for (int i = 0; i < NQW; i++) {
            int gn = n0 + qrW[i];
            int kbase = kt * GBK + qkW[i] * 16 + 2 * qtW[i];
            if (gn < N) {
                const float* p = W + (size_t)gn * K + kbase;
                vW[i][0] = (kbase     < K) ? p[0] : 0.f;
                vW[i][1] = (kbase + 1 < K) ? p[1] : 0.f;
                vW[i][2] = (kbase + 8 < K) ? p[8] : 0.f;
                vW[i][3] = (kbase + 9 < K) ? p[9] : 0.f;
            } else { vW[i][0] = vW[i][1] = vW[i][2] = vW[i][3] = 0.f; }
        }
    };
    auto store = [&](int buf) {
#pragma unroll
        for (int i = 0; i < NQA; i++)
            *(uint4*)&As[buf * SA_SZ + qoA[i]] =
                make_quad(vA[i][0], vA[i][1], vA[i][2], vA[i][3]);
#pragma unroll
        for (int i = 0; i < NQW; i++)
            *(uint4*)&Ws[buf * SW_SZ + qoW[i]] =
                make_quad(vW[i][0], vW[i][1], vW[i][2], vW[i][3]);
    };
    auto compute = [&](int buf) {
#pragma unroll
        for (int ks = 0; ks < 2; ks++) {
            uint32_t ah[4][4], al[4][4], bh[2][2], bl[2][2];
#pragma unroll
            for (int mt = 0; mt < 4; mt++) {
                int r = wm * 64 + mt * 16 + g;
                uint4 q0 = *(const uint4*)&As[buf * SA_SZ + quad_off(r,     ks, tg)];
                uint4 q1 = *(const uint4*)&As[buf * SA_SZ + quad_off(r + 8, ks, tg)];
                ah[mt][0] = q0.x; ah[mt][1] = q1.x; ah[mt][2] = q0.y; ah[mt][3] = q1.y;
                al[mt][0] = q0.z; al[mt][1] = q1.z; al[mt][2] = q0.w; al[mt][3] = q1.w;
            }
#pragma unroll
            for (int nt = 0; nt < 2; nt++) {
                int c = wn * 16 + nt * 8 + g;
                uint4 q = *(const uint4*)&Ws[buf * SW_SZ + quad_off(c, ks, tg)];
                bh[nt][0] = q.x; bh[nt][1] = q.y;
                bl[nt][0] = q.z; bl[nt][1] = q.w;
            }
#pragma unroll
            for (int mt = 0; mt < 4; mt++)
#pragma unroll
                for (int nt = 0; nt < 2; nt++) {
                    mma_bf16(acc[mt][nt], ah[mt][0], ah[mt][1], ah[mt][2], ah[mt][3],
                             bl[nt][0], bl[nt][1]);
                    mma_bf16(acc[mt][nt], al[mt][0], al[mt][1], al[mt][2], al[mt][3],
                             bh[nt][0], bh[nt][1]);
                    mma_bf16(acc[mt][nt], ah[mt][0], ah[mt][1], ah[mt][2], ah[mt][3],
                             bh[nt][0], bh[nt][1]);
                }
        }
    };

    loadg(0);
    store(0);
    __syncthreads();
    for (int kt = 0; kt < ntiles; kt++) {
        int buf = kt & 1;
        if (kt + 1 < ntiles) loadg(kt + 1);
        compute(buf);
        if (kt + 1 < ntiles) {
            store(buf ^ 1);
            __syncthreads();
        }
    }

#pragma unroll
    for (int mt = 0; mt < 4; mt++) {
        int r0 = m0 + wm * 64 + mt * 16 + g;
#pragma unroll
        for (int nt = 0; nt < 2; nt++) {
            int c0 = n0 + wn * 16 + nt * 8 + 2 * tg;
#pragma unroll
            for (int half = 0; half < 2; half++) {
                int r = r0 + half * 8;
#pragma unroll
                for (int jj = 0; jj < 2; jj++) {
                    int c = c0 + jj;
                    if (c < N) {
                        float v = acc[mt][nt][half * 2 + jj];
                        if (bias) v += bias[c];
                        size_t off = (size_t)r * ldc + c;
                        if (ACC) v += C[off];
                        C[off] = v;
                    }
                }
            }
        }
    }
}

// ============================================================
// Fused conv(4)+silu -> xproj(48) -> dt+softplus.  Block = 1 token.
// ============================================================
__global__ __launch_bounds__(128)
void fcx_k(const float* __restrict__ xz, const float* __restrict__ cw,
           const float* __restrict__ cb, const float* __restrict__ xw,
           const float* __restrict__ dtW, const float* __restrict__ dtb,
           float* __restrict__ xc, float* __restrict__ dbl, float* __restrict__ dt)
{
    __shared__ float4 sxc[128];
    __shared__ float  sdbl[48];

    int row = blockIdx.x;
    int t = row & (SEQ - 1);
    int tid = threadIdx.x;
    int warp = tid >> 5, lane = tid & 31;
    int d = tid * 4;

    float4 w0 = *(const float4*)(cw + (d    ) * 4);
    float4 w1 = *(const float4*)(cw + (d + 1) * 4);
    float4 w2 = *(const float4*)(cw + (d + 2) * 4);
    float4 w3 = *(const float4*)(cw + (d + 3) * 4);
    float4 acc = *(const float4*)(cb + d);
    const float* base = xz + (size_t)row * (2*D_INNER) + d;
#pragma unroll
    for (int k = 0; k < 4; k++) {
        int tt = t - 3 + k;
        if (tt >= 0) {
            float4 xv = *(const float4*)(base + (ptrdiff_t)(k - 3) * (2*D_INNER));
            acc.x = fmaf(xv.x, ((const float*)&w0)[k], acc.x);
            acc.y = fmaf(xv.y, ((const float*)&w1)[k], acc.y);
            acc.z = fmaf(xv.z, ((const float*)&w2)[k], acc.z);
            acc.w = fmaf(xv.w, ((const float*)&w3)[k], acc.w);
        }
    }
    float4 o;
    o.x = acc.x / (1.f + __expf(-acc.x));
    o.y = acc.y / (1.f + __expf(-acc.y));
    o.z = acc.z / (1.f + __expf(-acc.z));
    o.w = acc.w / (1.f + __expf(-acc.w));
    sxc[tid] = o;
    *(float4*)(xc + (size_t)row * D_INNER + d) = o;
    __syncthreads();

#pragma unroll
    for (int i = 0; i < 12; i++) {
        int n = warp * 12 + i;
        const float4* wr = (const float4*)(xw + (size_t)n * D_INNER);
        float s = 0.f;
#pragma unroll
        for (int j = 0; j < 4; j++) {
            float4 x = sxc[lane + 32 * j];
            float4 w = wr[lane + 32 * j];
            s = fmaf(x.x, w.x, s);
            s = fmaf(x.y, w.y, s);
            s = fmaf(x.z, w.z, s);
            s = fmaf(x.w, w.w, s);
        }
#pragma unroll
        for (int off = 16; off > 0; off >>= 1)
            s += __shfl_xor_sync(0xffffffffu, s, off);
        if (lane == 0) sdbl[n] = s;
    }
    __syncthreads();

    if (tid < 48) dbl[(size_t)row * 48 + tid] = sdbl[tid];

    float rv[16];
#pragma unroll
    for (int j = 0; j < 16; j++) rv[j] = sdbl[j];
    float4 sp = *(const float4*)(dtb + d);
    float* sv = (float*)&sp;
#pragma unroll
    for (int dd = 0; dd < 4; dd++) {
        const float4* w = (const float4*)(dtW + (size_t)(d + dd) * DT_RANK);
        float s = sv[dd];
#pragma unroll
        for (int j = 0; j < 4; j++) {
            float4 wv = w[j];
            s = fmaf(rv[j*4+0], wv.x, s);
            s = fmaf(rv[j*4+1], wv.y, s);
            s = fmaf(rv[j*4+2], wv.z, s);
            s = fmaf(rv[j*4+3], wv.w, s);
        }
        sv[dd] = (s > 20.f) ? s : log1pf(__expf(s));
    }
    *(float4*)(dt + (size_t)row * D_INNER + d) = sp;
}

// ---------------- layernorm (warp per row of 256, vectorized) ----------------
__global__ void ln_k(const float* __restrict__ x, const float* __restrict__ g,
                     const float* __restrict__ b, float* __restrict__ y)
{
    int warp = (blockIdx.x * blockDim.x + threadIdx.x) >> 5;
    int lane = threadIdx.x & 31;
    if (warp >= M_ROWS) return;
    const float4* xr = (const float4*)(x + (size_t)warp * D_MODEL);
    float4 v[2];
    float s = 0.f, s2 = 0.f;
#pragma unroll
    for (int i = 0; i < 2; i++) {
        v[i] = xr[lane + i * 32];
        s += v[i].x + v[i].y + v[i].z + v[i].w;
        s2 = fmaf(v[i].x, v[i].x, s2);
        s2 = fmaf(v[i].y, v[i].y, s2);
        s2 = fmaf(v[i].z, v[i].z, s2);
        s2 = fmaf(v[i].w, v[i].w, s2);
    }
#pragma unroll
    for (int o = 16; o > 0; o >>= 1) {
        s  += __shfl_xor_sync(0xffffffffu, s,  o);
        s2 += __shfl_xor_sync(0xffffffffu, s2, o);
    }
    float mu = s * (1.f / D_MODEL);
    float var = s2 * (1.f / D_MODEL) - mu * mu;
    float inv = rsqrtf(var + 1e-5f);
    float4* yr = (float4*)(y + (size_t)warp * D_MODEL);
#pragma unroll
    for (int i = 0; i < 2; i++) {
        int c = (lane + i * 32) * 4;
        float4 gg = *(const float4*)(g + c);
        float4 bb = *(const float4*)(b + c);
        float4 o;
        o.x = (v[i].x - mu) * inv * gg.x + bb.x;
        o.y = (v[i].y - mu) * inv * gg.y + bb.y;
        o.z = (v[i].z - mu) * inv * gg.z + bb.z;
        o.w = (v[i].w - mu) * inv * gg.w + bb.w;
        yr[lane + i * 32] = o;
    }
}

// ============================================================
// FUSED selective scan: pass1 + in-block combine + pass2.
// Block = 512 threads = 16 warps; block <-> (batch b, 8-channel dgrp);
// warp w <-> chunk w. 512 blocks total.
// ============================================================
__device__ __forceinline__ void exp_powers(bool FAST, float dtv, int sg,
                                           float a0, float a1, float a2, float a3,
                                           float& e0, float& e1, float& e2, float& e3)
{
    if (FAST) {
        float p  = __expf(-dtv);
        float p2 = p * p;
        float p4 = p2 * p2;
        float p8 = p4 * p4;
        float b1 = (sg & 1) ? p4 : 1.f;
        float b2 = (sg & 2) ? p8 : 1.f;
        e0 = b1 * b2 * p;
        e1 = e0 * p;
        e2 = e1 * p;
        e3 = e2 * p;
    } else {
        e0 = __expf(dtv * a0);
        e1 = __expf(dtv * a1);
        e2 = __expf(dtv * a2);
        e3 = __expf(dtv * a3);
    }
}

template<bool FAST>
__device__ __forceinline__ void p1_body(
    const float* pdt, const float* pxc, const float* pbc,
    int sg, float a0, float a1, float a2, float a3,
    float4& hout, float4& pout)
{
    float h0=0.f,h1=0.f,h2=0.f,h3=0.f;
    float P0=1.f,P1=1.f,P2=1.f,P3=1.f;
    float dbuf[4], xbuf[4]; float4 Bbuf[4];
#pragma unroll
    for (int j = 0; j < 4; j++) {
        dbuf[j] = pdt[(size_t)j * D_INNER];
        xbuf[j] = pxc[(size_t)j * D_INNER];
        Bbuf[j] = *(const float4*)(pbc + (size_t)j * 48);
    }
    for (int t = 0; t < CH; t += 4) {
#pragma unroll
        for (int j = 0; j < 4; j++) {
            float dtv = dbuf[j], xcv = xbuf[j]; float4 B = Bbuf[j];
            int tn = t + 4 + j; if (tn > CH - 1) tn = CH - 1;
            dbuf[j] = pdt[(size_t)tn * D_INNER];
            xbuf[j] = pxc[(size_t)tn * D_INNER];
            Bbuf[j] = *(const float4*)(pbc + (size_t)tn * 48);
            float u = dtv * xcv;
            float e0,e1,e2,e3;
            exp_powers(FAST, dtv, sg, a0,a1,a2,a3, e0,e1,e2,e3);
            h0 = fmaf(h0, e0, u * B.x);  P0 *= e0;
            h1 = fmaf(h1, e1, u * B.y);  P1 *= e1;
            h2 = fmaf(h2, e2, u * B.z);  P2 *= e2;
            h3 = fmaf(h3, e3, u * B.w);  P3 *= e3;
        }
    }
    hout = make_float4(h0,h1,h2,h3);
    pout = make_float4(P0,P1,P2,P3);
}

template<bool FAST>
__device__ __forceinline__ void p2_body(
    const float* pdt, const float* pxc, const float* pz, const float* pbc,
    float* py, int sg, float a0, float a1, float a2, float a3, float Dd, float4 hin)
{
    float h0=hin.x, h1=hin.y, h2=hin.z, h3=hin.w;
    float dbuf[4], xbuf[4], zbuf[4]; float4 Bbuf[4], Cbuf[4];
#pragma unroll
    for (int j = 0; j < 4; j++) {
        dbuf[j] = pdt[(size_t)j * D_INNER];
        xbuf[j] = pxc[(size_t)j * D_INNER];
        zbuf[j] = pz [(size_t)j * (2*D_INNER)];
        Bbuf[j] = *(const float4*)(pbc + (size_t)j * 48);
        Cbuf[j] = *(const float4*)(pbc + (size_t)j * 48 + D_STATE);
    }
    for (int t = 0; t < CH; t += 4) {
        float yp[4], xs[4], zs[4];
#pragma unroll
        for (int j = 0; j < 4; j++) {
            float dtv = dbuf[j], xcv = xbuf[j], zv = zbuf[j];
            float4 B = Bbuf[j], Cv = Cbuf[j];
            int tn = t + 4 + j; if (tn > CH - 1) tn = CH - 1;
            dbuf[j] = pdt[(size_t)tn * D_INNER];
            xbuf[j] = pxc[(size_t)tn * D_INNER];
            zbuf[j] = pz [(size_t)tn * (2*D_INNER)];
            Bbuf[j] = *(const float4*)(pbc + (size_t)tn * 48);
            Cbuf[j] = *(const float4*)(pbc + (size_t)tn * 48 + D_STATE);
            float u = dtv * xcv;
            float e0,e1,e2,e3;
            exp_powers(FAST, dtv, sg, a0,a1,a2,a3, e0,e1,e2,e3);
            h0 = fmaf(h0, e0, u * B.x);
            h1 = fmaf(h1, e1, u * B.y);
            h2 = fmaf(h2, e2, u * B.z);
            h3 = fmaf(h3, e3, u * B.w);
            float y = h0 * Cv.x;
            y = fmaf(h1, Cv.y, y);
            y = fmaf(h2, Cv.z, y);
            y = fmaf(h3, Cv.w, y);
            yp[j] = y; xs[j] = xcv; zs[j] = zv;
        }
#pragma unroll
        for (int j = 0; j < 4; j++)
            yp[j] += __shfl_xor_sync(0xffffffffu, yp[j], 1);
#pragma unroll
        for (int j = 0; j < 4; j++)
            yp[j] += __shfl_xor_sync(0xffffffffu, yp[j], 2);
        if (sg == 0) {
#pragma unroll
            for (int j = 0; j < 4; j++) {
                float yy = fmaf(xs[j], Dd, yp[j]);
                float sz = zs[j] / (1.f + __expf(-zs[j]));
                py[(size_t)(t + j) * D_INNER] = yy * sz;
            }
        }
    }
}

__global__ __launch_bounds__(512)
void scan_f(const float* __restrict__ dt, const float* __restrict__ xc,
            const float* __restrict__ dbl, const float* __restrict__ xz,
            const float* __restrict__ A_log, const float* __restrict__ Dv,
            float* __restrict__ yb)
{
    __shared__ float4 sh[NCH][32];   // per-chunk h_end
    __shared__ float4 sp[NCH][32];   // per-chunk P_end
    __shared__ float4 sc[NCH][32];   // carry entering each chunk

    int blk = blockIdx.x;            // 512 blocks
    int b = blk >> 6;
    int dgrp = blk & 63;
    int chunk = threadIdx.x >> 5;    // warp = chunk
    int lane = threadIdx.x & 31;
    int dl = lane >> 2, sg = lane & 3;
    int d = dgrp * 8 + dl;
    int t0 = chunk * CH;

    const float* pdt = dt  + ((size_t)b * SEQ + t0) * D_INNER + d;
    const float* pxc = xc  + ((size_t)b * SEQ + t0) * D_INNER + d;
    const float* pz  = xz  + ((size_t)b * SEQ + t0) * (2*D_INNER) + D_INNER + d;
    const float* pbc = dbl + ((size_t)b * SEQ + t0) * 48 + DT_RANK + 4 * sg;
    float* py        = yb  + ((size_t)b * SEQ + t0) * D_INNER + d;

    // A constants + fast check
    float4 al = *(const float4*)(A_log + d * D_STATE + 4 * sg);
    float a0 = -expf(al.x), a1 = -expf(al.y), a2 = -expf(al.z), a3 = -expf(al.w);
    float n0 = (float)(4 * sg + 1);
    bool ok = fabsf(a0 + n0)      < 1e-3f * n0 &&
              fabsf(a1 + (n0+1)) < 1e-3f * (n0+1) &&
              fabsf(a2 + (n0+2)) < 1e-3f * (n0+2) &&
              fabsf(a3 + (n0+3)) < 1e-3f * (n0+3);
    bool fast = __all_sync(0xffffffffu, ok);
    float Dd = Dv[d];

    // ---- pass 1 ----
    float4 ho, po;
    if (fast) p1_body<true >(pdt, pxc, pbc, sg, a0,a1,a2,a3, ho, po);
    else      p1_body<false>(pdt, pxc, pbc, sg, a0,a1,a2,a3, ho, po);
    sh[chunk][lane] = ho;
    sp[chunk][lane] = po;
    __syncthreads();

    // ---- combine (first warp; thread = lane slot, serial over chunks) ----
    if (threadIdx.x < 32) {
        float4 c = make_float4(0.f, 0.f, 0.f, 0.f);
#pragma unroll
        for (int ch = 0; ch < NCH; ch++) {
            sc[ch][threadIdx.x] = c;
            float4 hh = sh[ch][threadIdx.x];
            float4 pp = sp[ch][threadIdx.x];
            c.x = fmaf(pp.x, c.x, hh.x);
            c.y = fmaf(pp.y, c.y, hh.y);
            c.z = fmaf(pp.z, c.z, hh.z);
            c.w = fmaf(pp.w, c.w, hh.w);
        }
    }
    __syncthreads();

    // ---- pass 2 ----
    float4 hin = sc[chunk][lane];
    if (fast) p2_body<true >(pdt, pxc, pz, pbc, py, sg, a0,a1,a2,a3, Dd, hin);
    else      p2_body<false>(pdt, pxc, pz, pbc, py, sg, a0,a1,a2,a3, Dd, hin);
}

// ---------------- host side ----------------
static inline void launch_gemm(const float* A, const float* W, const float* bias,
                               float* C, int M, int N, int K, int ldc, bool acc)
{
    dim3 grid((N + GBN - 1) / GBN, (M + GBM - 1) / GBM);
    size_t smem = SMEM_WORDS * sizeof(uint32_t);
    if (acc) gemm_bf16<true><<<grid, 256, smem>>>(A, W, bias, C, M, N, K, ldc);
    else     gemm_bf16<false><<<grid, 256, smem>>>(A, W, bias, C, M, N, K, ldc);
}

extern "C" void kernel_launch(void* const* d_in, const int* in_sizes, int n_in,
                              void* d_out, int out_size)
{
    const float* wav    = (const float*)d_in[0];
    const float* lib    = (const float*)d_in[1];
    const float* w2v_W  = (const float*)d_in[2];
    const float* w2v_b  = (const float*)d_in[3];
    const float* lib_W  = (const float*)d_in[4];
    const float* lib_b  = (const float*)d_in[5];
    const float* fuse_W = (const float*)d_in[6];
    const float* fuse_b = (const float*)d_in[7];
    const float* proj_W = (const float*)d_in[8];
    const float* proj_b = (const float*)d_in[9];
    const float* ln_g   = (const float*)d_in[10];
    const float* ln_b   = (const float*)d_in[11];
    const float* in_W   = (const float*)d_in[12];
    const float* conv_W = (const float*)d_in[13];
    const float* conv_b = (const float*)d_in[14];
    const float* xproj_W= (const float*)d_in[15];
    const float* dt_W   = (const float*)d_in[16];
    const float* dt_b   = (const float*)d_in[17];
    const float* A_log  = (const float*)d_in[18];
    const float* D_vec  = (const float*)d_in[19];
    const float* out_W  = (const float*)d_in[20];
    const float* fnorm_g= (const float*)d_in[21];
    const float* fnorm_b= (const float*)d_in[22];
    float* out = (float*)d_out;

    size_t smem = SMEM_WORDS * sizeof(uint32_t);
    cudaFuncSetAttribute(gemm_bf16<false>, cudaFuncAttributeMaxDynamicSharedMemorySize, (int)smem);
    cudaFuncSetAttribute(gemm_bf16<true>,  cudaFuncAttributeMaxDynamicSharedMemorySize, (int)smem);

    float *wl, *tb, *hb, *xln, *xzb, *xcb, *dblb, *dtb2, *yb;
    cudaGetSymbolAddress((void**)&wl,   g_wl);
    cudaGetSymbolAddress((void**)&tb,   g_t);
    cudaGetSymbolAddress((void**)&hb,   g_h);
    cudaGetSymbolAddress((void**)&xln,  g_xln);
    cudaGetSymbolAddress((void**)&xzb,  g_xz);
    cudaGetSymbolAddress((void**)&xcb,  g_xc);
    cudaGetSymbolAddress((void**)&dblb, g_dbl);
    cudaGetSymbolAddress((void**)&dtb2, g_dt);
    cudaGetSymbolAddress((void**)&yb,   g_y);

    const int M = M_ROWS;

    launch_gemm(wav, w2v_W, w2v_b, wl,           M, D_MODEL, W2V_DIM,   2*D_MODEL, false);
    launch_gemm(lib, lib_W, lib_b, wl + D_MODEL, M, D_MODEL, LIB_DIM,   2*D_MODEL, false);
    launch_gemm(wl,  fuse_W, fuse_b, tb,         M, D_MODEL, 2*D_MODEL, D_MODEL,   false);
    launch_gemm(tb,  proj_W, proj_b, hb,         M, D_MODEL, D_MODEL,   D_MODEL,   false);

    for (int i = 0; i < N_LAYERS; i++) {
        const float* lg  = ln_g   + i * D_MODEL;
        const float* lb  = ln_b   + i * D_MODEL;
        const float* iw  = in_W   + (size_t)i * 2*D_INNER * D_MODEL;
        const float* cw  = conv_W + (size_t)i * D_INNER * 4;
        const float* cb  = conv_b + (size_t)i * D_INNER;
        const float* xw  = xproj_W+ (size_t)i * (DT_RANK + 2*D_STATE) * D_INNER;
        const float* dw  = dt_W   + (size_t)i * D_INNER * DT_RANK;
        const float* db  = dt_b   + (size_t)i * D_INNER;
        const float* al  = A_log  + (size_t)i * D_INNER * D_STATE;
        const float* dv  = D_vec  + (size_t)i * D_INNER;
        const float* ow  = out_W  + (size_t)i * D_MODEL * D_INNER;

        ln_k<<<M_ROWS / 8, 256>>>(hb, lg, lb, xln);
        launch_gemm(xln, iw, nullptr, xzb, M, 2*D_INNER, D_MODEL, 2*D_INNER, false);
        fcx_k<<<M_ROWS, 128>>>(xzb, cw, cb, xw, dw, db, xcb, dblb, dtb2);
        scan_f<<<512, 512>>>(dtb2, xcb, dblb, xzb, al, dv, yb);
        launch_gemm(yb, ow, nullptr, hb, M, D_MODEL, D_INNER, D_MODEL, true);
    }

    ln_k<<<M_ROWS / 8, 256>>>(hb, fnorm_g, fnorm_b, out);
}

// round 17
// speedup vs baseline: 1.0972x; 1.0972x over previous
#include <cuda_runtime.h>
#include <cuda_bf16.h>
#include <math.h>
#include <stdint.h>

// ---------------- problem constants ----------------
#define BATCH   8
#define SEQ     1024
#define M_ROWS  (BATCH*SEQ)        // 8192
#define D_MODEL 256
#define D_INNER 512
#define D_STATE 16
#define DT_RANK 16
#define N_LAYERS 4
#define W2V_DIM 768
#define LIB_DIM 93
#define NCH     16                 // scan chunks
#define CH      (SEQ/NCH)          // 64

// ---------------- scratch buffers ----------------
__device__ float g_wl [M_ROWS * (2*D_MODEL)];
__device__ float g_t  [M_ROWS * D_MODEL];
__device__ float g_h  [M_ROWS * D_MODEL];
__device__ float g_xln[M_ROWS * D_MODEL];
__device__ float g_xz [M_ROWS * (2*D_INNER)];
__device__ float g_xc [M_ROWS * D_INNER];
__device__ float g_dbl[M_ROWS * (DT_RANK+2*D_STATE)];
__device__ float g_dt [M_ROWS * D_INNER];
__device__ float g_y  [M_ROWS * D_INNER];
__device__ float g_hend [BATCH * NCH * D_INNER * D_STATE];
__device__ float g_pend [BATCH * NCH * D_INNER * D_STATE];
__device__ float g_carry[BATCH * NCH * D_INNER * D_STATE];

// ============================================================
// bf16-split tensor-core GEMM (R12 winner: BK=32 + XOR swizzle)
// + float2 global loads (only when K is even -> 8B-aligned rows)
// + float2 epilogue (ldc, c0 always even).
// ============================================================
#define GBM 128
#define GBN 64
#define GBK 32
#define GROW 32

#define SA_SZ (GBM*GROW)
#define SW_SZ (GBN*GROW)
#define SMEM_WORDS (2*SA_SZ + 2*SW_SZ)   // 48KB

#define NQA 4
#define NQW 2

__device__ __forceinline__ void mma_bf16(float c[4], uint32_t a0, uint32_t a1,
                                         uint32_t a2, uint32_t a3,
                                         uint32_t b0, uint32_t b1) {
    asm volatile(
        "mma.sync.aligned.m16n8k16.row.col.f32.bf16.bf16.f32 "
        "{%0,%1,%2,%3}, {%4,%5,%6,%7}, {%8,%9}, {%0,%1,%2,%3};"
        : "+f"(c[0]), "+f"(c[1]), "+f"(c[2]), "+f"(c[3])
        : "r"(a0), "r"(a1), "r"(a2), "r"(a3), "r"(b0), "r"(b1));
}

__device__ __forceinline__ uint32_t pack_bf(float v0, float v1) {
    __nv_bfloat162 p = __halves2bfloat162(__float2bfloat16_rn(v0),
                                          __float2bfloat16_rn(v1));
    return *(uint32_t*)&p;
}

__device__ __forceinline__ uint4 make_quad(float v0, float v1, float v2, float v3) {
    float h0 = __bfloat162float(__float2bfloat16_rn(v0));
    float h1 = __bfloat162float(__float2bfloat16_rn(v1));
    float h2 = __bfloat162float(__float2bfloat16_rn(v2));
    float h3 = __bfloat162float(__float2bfloat16_rn(v3));
    uint4 q;
    q.x = pack_bf(v0, v1);
    q.y = pack_bf(v2, v3);
    q.z = pack_bf(v0 - h0, v1 - h1);
    q.w = pack_bf(v2 - h2, v3 - h3);
    return q;
}

__device__ __forceinline__ int quad_off(int row, int ks, int tg) {
    return row * GROW + (((ks << 4) + (tg << 2)) ^ ((row & 1) << 4));
}

template<bool ACC>
__global__ __launch_bounds__(256, 2)
void gemm_bf16(const float* __restrict__ A, const float* __restrict__ W,
               const float* __restrict__ bias, float* __restrict__ C,
               int M, int N, int K, int ldc)
{
    extern __shared__ uint32_t smem[];
    uint32_t* As = smem;
    uint32_t* Ws = smem + 2 * SA_SZ;

    const int tid  = threadIdx.x;
    const int lane = tid & 31;
    const int g    = lane >> 2;
    const int tg   = lane & 3;
    const int warp = tid >> 5;
    const int wm   = warp >> 2;
    const int wn   = warp & 3;
    const int m0   = blockIdx.y * GBM;
    const int n0   = blockIdx.x * GBN;
    const bool k2  = (K & 1) == 0;     // rows 8B-aligned -> float2 loads legal

    float acc[4][2][4];
#pragma unroll
    for (int i = 0; i < 4; i++)
#pragma unroll
        for (int j = 0; j < 2; j++)
#pragma unroll
            for (int l = 0; l < 4; l++) acc[i][j][l] = 0.f;

    const int ntiles = (K + GBK - 1) / GBK;

    int qrA[NQA], qkA[NQA], qtA[NQA], qoA[NQA];
    int qrW[NQW], qkW[NQW], qtW[NQW], qoW[NQW];
#pragma unroll
    for (int i = 0; i < NQA; i++) {
        int q = tid + i * 256;
        qrA[i] = q >> 3; qkA[i] = (q >> 2) & 1; qtA[i] = q & 3;
        qoA[i] = quad_off(qrA[i], qkA[i], qtA[i]);
    }
#pragma unroll
    for (int i = 0; i < NQW; i++) {
        int q = tid + i * 256;
        qrW[i] = q >> 3; qkW[i] = (q >> 2) & 1; qtW[i] = q & 3;
        qoW[i] = quad_off(qrW[i], qkW[i], qtW[i]);
    }

    float vA[NQA][4], vW[NQW][4];

    auto loadg = [&](int kt) {
#pragma unroll
        for (int i = 0; i < NQA; i++) {
            int kbase = kt * GBK + qkA[i] * 16 + 2 * qtA[i];
            const float* p = A + (size_t)(m0 + qrA[i]) * K + kbase;
            if (k2 && kbase + 9 < K) {      // fast path: 2x LDG.64
                float2 u0 = *(const float2*)p;
                float2 u1 = *(const float2*)(p + 8);
                vA[i][0] = u0.x; vA[i][1] = u0.y;
                vA[i][2] = u1.x; vA[i][3] = u1.y;
            } else {
                vA[i][0] = (kbase     < K) ? p[0] : 0.f;
                vA[i][1] = (kbase + 1 < K) ? p[1] : 0.f;
                vA[i][2] = (kbase + 8 < K) ? p[8] : 0.f;
                vA[i][3] = (kbase + 9 < K) ? p[9] : 0.f;
            }
        }
#pragma unroll
        for (int i = 0; i < NQW; i++) {
            int gn = n0 + qrW[i];
            int kbase = kt * GBK + qkW[i] * 16 + 2 * qtW[i];
            if (gn < N) {
                const float* p = W + (size_t)gn * K + kbase;
                if (k2 && kbase + 9 < K) {
                    float2 u0 = *(const float2*)p;
                    float2 u1 = *(const float2*)(p + 8);
                    vW[i][0] = u0.x; vW[i][1] = u0.y;
                    vW[i][2] = u1.x; vW[i][3] = u1.y;
                } else {
                    vW[i][0] = (kbase     < K) ? p[0] : 0.f;
                    vW[i][1] = (kbase + 1 < K) ? p[1] : 0.f;
                    vW[i][2] = (kbase + 8 < K) ? p[8] : 0.f;
                    vW[i][3] = (kbase + 9 < K) ? p[9] : 0.f;
                }
            } else { vW[i][0] = vW[i][1] = vW[i][2] = vW[i][3] = 0.f; }
        }
    };
    auto store = [&](int buf) {
#pragma unroll
        for (int i = 0; i < NQA; i++)
            *(uint4*)&As[buf * SA_SZ + qoA[i]] =
                make_quad(vA[i][0], vA[i][1], vA[i][2], vA[i][3]);
#pragma unroll
        for (int i = 0; i < NQW; i++)
            *(uint4*)&Ws[buf * SW_SZ + qoW[i]] =
                make_quad(vW[i][0], vW[i][1], vW[i][2], vW[i][3]);
    };
    auto compute = [&](int buf) {
#pragma unroll
        for (int ks = 0; ks < 2; ks++) {
            uint32_t ah[4][4], al[4][4], bh[2][2], bl[2][2];
#pragma unroll
            for (int mt = 0; mt < 4; mt++) {
                int r = wm * 64 + mt * 16 + g;
                uint4 q0 = *(const uint4*)&As[buf * SA_SZ + quad_off(r,     ks, tg)];
                uint4 q1 = *(const uint4*)&As[buf * SA_SZ + quad_off(r + 8, ks, tg)];
                ah[mt][0] = q0.x; ah[mt][1] = q1.x; ah[mt][2] = q0.y; ah[mt][3] = q1.y;
                al[mt][0] = q0.z; al[mt][1] = q1.z; al[mt][2] = q0.w; al[mt][3] = q1.w;
            }
#pragma unroll
            for (int nt = 0; nt < 2; nt++) {
                int c = wn * 16 + nt * 8 + g;
                uint4 q = *(const uint4*)&Ws[buf * SW_SZ + quad_off(c, ks, tg)];
                bh[nt][0] = q.x; bh[nt][1] = q.y;
                bl[nt][0] = q.z; bl[nt][1] = q.w;
            }
#pragma unroll
            for (int mt = 0; mt < 4; mt++)
#pragma unroll
                for (int nt = 0; nt < 2; nt++) {
                    mma_bf16(acc[mt][nt], ah[mt][0], ah[mt][1], ah[mt][2], ah[mt][3],
                             bl[nt][0], bl[nt][1]);
                    mma_bf16(acc[mt][nt], al[mt][0], al[mt][1], al[mt][2], al[mt][3],
                             bh[nt][0], bh[nt][1]);
                    mma_bf16(acc[mt][nt], ah[mt][0], ah[mt][1], ah[mt][2], ah[mt][3],
                             bh[nt][0], bh[nt][1]);
                }
        }
    };

    loadg(0);
    store(0);
    __syncthreads();
    for (int kt = 0; kt < ntiles; kt++) {
        int buf = kt & 1;
        if (kt + 1 < ntiles) loadg(kt + 1);
        compute(buf);
        if (kt + 1 < ntiles) {
            store(buf ^ 1);
            __syncthreads();
        }
    }

    // epilogue: float2 per (half, jj-pair); ldc and c0 always even here
#pragma unroll
    for (int mt = 0; mt < 4; mt++) {
        int r0 = m0 + wm * 64 + mt * 16 + g;
#pragma unroll
        for (int nt = 0; nt < 2; nt++) {
            int c0 = n0 + wn * 16 + nt * 8 + 2 * tg;
            if (c0 + 1 < N) {
                float2 bv = make_float2(0.f, 0.f);
                if (bias) bv = *(const float2*)(bias + c0);
#pragma unroll
                for (int half = 0; half < 2; half++) {
                    int r = r0 + half * 8;
                    float2 v;
                    v.x = acc[mt][nt][half * 2    ] + bv.x;
                    v.y = acc[mt][nt][half * 2 + 1] + bv.y;
                    float* p = C + (size_t)r * ldc + c0;
                    if (ACC) {
                        float2 o = *(const float2*)p;
                        v.x += o.x; v.y += o.y;
                    }
                    *(float2*)p = v;
                }
            } else {
#pragma unroll
                for (int half = 0; half < 2; half++) {
                    int r = r0 + half * 8;
#pragma unroll
                    for (int jj = 0; jj < 2; jj++) {
                        int c = c0 + jj;
                        if (c < N) {
                            float v = acc[mt][nt][half * 2 + jj];
                            if (bias) v += bias[c];
                            size_t off = (size_t)r * ldc + c;
                            if (ACC) v += C[off];
                            C[off] = v;
                        }
                    }
                }
            }
        }
    }
}

// ============================================================
// Fused conv(4)+silu -> xproj(48) -> dt+softplus.  Block = 1 token.
// ============================================================
__global__ __launch_bounds__(128)
void fcx_k(const float* __restrict__ xz, const float* __restrict__ cw,
           const float* __restrict__ cb, const float* __restrict__ xw,
           const float* __restrict__ dtW, const float* __restrict__ dtb,
           float* __restrict__ xc, float* __restrict__ dbl, float* __restrict__ dt)
{
    __shared__ float4 sxc[128];
    __shared__ float  sdbl[48];

    int row = blockIdx.x;
    int t = row & (SEQ - 1);
    int tid = threadIdx.x;
    int warp = tid >> 5, lane = tid & 31;
    int d = tid * 4;

    float4 w0 = *(const float4*)(cw + (d    ) * 4);
    float4 w1 = *(const float4*)(cw + (d + 1) * 4);
    float4 w2 = *(const float4*)(cw + (d + 2) * 4);
    float4 w3 = *(const float4*)(cw + (d + 3) * 4);
    float4 acc = *(const float4*)(cb + d);
    const float* base = xz + (size_t)row * (2*D_INNER) + d;
#pragma unroll
    for (int k = 0; k < 4; k++) {
        int tt = t - 3 + k;
        if (tt >= 0) {
            float4 xv = *(const float4*)(base + (ptrdiff_t)(k - 3) * (2*D_INNER));
            acc.x = fmaf(xv.x, ((const float*)&w0)[k], acc.x);
            acc.y = fmaf(xv.y, ((const float*)&w1)[k], acc.y);
            acc.z = fmaf(xv.z, ((const float*)&w2)[k], acc.z);
            acc.w = fmaf(xv.w, ((const float*)&w3)[k], acc.w);
        }
    }
    float4 o;
    o.x = acc.x / (1.f + __expf(-acc.x));
    o.y = acc.y / (1.f + __expf(-acc.y));
    o.z = acc.z / (1.f + __expf(-acc.z));
    o.w = acc.w / (1.f + __expf(-acc.w));
    sxc[tid] = o;
    *(float4*)(xc + (size_t)row * D_INNER + d) = o;
    __syncthreads();

#pragma unroll
    for (int i = 0; i < 12; i++) {
        int n = warp * 12 + i;
        const float4* wr = (const float4*)(xw + (size_t)n * D_INNER);
        float s = 0.f;
#pragma unroll
        for (int j = 0; j < 4; j++) {
            float4 x = sxc[lane + 32 * j];
            float4 w = wr[lane + 32 * j];
            s = fmaf(x.x, w.x, s);
            s = fmaf(x.y, w.y, s);
            s = fmaf(x.z, w.z, s);
            s = fmaf(x.w, w.w, s);
        }
#pragma unroll
        for (int off = 16; off > 0; off >>= 1)
            s += __shfl_xor_sync(0xffffffffu, s, off);
        if (lane == 0) sdbl[n] = s;
    }
    __syncthreads();

    if (tid < 48) dbl[(size_t)row * 48 + tid] = sdbl[tid];

    float rv[16];
#pragma unroll
    for (int j = 0; j < 16; j++) rv[j] = sdbl[j];
    float4 sp = *(const float4*)(dtb + d);
    float* sv = (float*)&sp;
#pragma unroll
    for (int dd = 0; dd < 4; dd++) {
        const float4* w = (const float4*)(dtW + (size_t)(d + dd) * DT_RANK);
        float s = sv[dd];
#pragma unroll
        for (int j = 0; j < 4; j++) {
            float4 wv = w[j];
            s = fmaf(rv[j*4+0], wv.x, s);
            s = fmaf(rv[j*4+1], wv.y, s);
            s = fmaf(rv[j*4+2], wv.z, s);
            s = fmaf(rv[j*4+3], wv.w, s);
        }
        sv[dd] = (s > 20.f) ? s : log1pf(__expf(s));
    }
    *(float4*)(dt + (size_t)row * D_INNER + d) = sp;
}

// ---------------- layernorm (warp per row of 256, vectorized) ----------------
__global__ void ln_k(const float* __restrict__ x, const float* __restrict__ g,
                     const float* __restrict__ b, float* __restrict__ y)
{
    int warp = (blockIdx.x * blockDim.x + threadIdx.x) >> 5;
    int lane = threadIdx.x & 31;
    if (warp >= M_ROWS) return;
    const float4* xr = (const float4*)(x + (size_t)warp * D_MODEL);
    float4 v[2];
    float s = 0.f, s2 = 0.f;
#pragma unroll
    for (int i = 0; i < 2; i++) {
        v[i] = xr[lane + i * 32];
        s += v[i].x + v[i].y + v[i].z + v[i].w;
        s2 = fmaf(v[i].x, v[i].x, s2);
        s2 = fmaf(v[i].y, v[i].y, s2);
        s2 = fmaf(v[i].z, v[i].z, s2);
        s2 = fmaf(v[i].w, v[i].w, s2);
    }
#pragma unroll
    for (int o = 16; o > 0; o >>= 1) {
        s  += __shfl_xor_sync(0xffffffffu, s,  o);
        s2 += __shfl_xor_sync(0xffffffffu, s2, o);
    }
    float mu = s * (1.f / D_MODEL);
    float var = s2 * (1.f / D_MODEL) - mu * mu;
    float inv = rsqrtf(var + 1e-5f);
    float4* yr = (float4*)(y + (size_t)warp * D_MODEL);
#pragma unroll
    for (int i = 0; i < 2; i++) {
        int c = (lane + i * 32) * 4;
        float4 gg = *(const float4*)(g + c);
        float4 bb = *(const float4*)(b + c);
        float4 o;
        o.x = (v[i].x - mu) * inv * gg.x + bb.x;
        o.y = (v[i].y - mu) * inv * gg.y + bb.y;
        o.z = (v[i].z - mu) * inv * gg.z + bb.z;
        o.w = (v[i].w - mu) * inv * gg.w + bb.w;
        yr[lane + i * 32] = o;
    }
}

// ============================================================
// Chunked selective scan (R12: separate p1 / combine / p2), NCH=16
// ============================================================
__device__ __forceinline__ void exp_powers(bool FAST, float dtv, int sg,
                                           float a0, float a1, float a2, float a3,
                                           float& e0, float& e1, float& e2, float& e3)
{
    if (FAST) {
        float p  = __expf(-dtv);
        float p2 = p * p;
        float p4 = p2 * p2;
        float p8 = p4 * p4;
        float b1 = (sg & 1) ? p4 : 1.f;
        float b2 = (sg & 2) ? p8 : 1.f;
        e0 = b1 * b2 * p;
        e1 = e0 * p;
        e2 = e1 * p;
        e3 = e2 * p;
    } else {
        e0 = __expf(dtv * a0);
        e1 = __expf(dtv * a1);
        e2 = __expf(dtv * a2);
        e3 = __expf(dtv * a3);
    }
}

__device__ __forceinline__ bool fast_check(const float* A_log, int d, int sg,
                                           float& a0, float& a1, float& a2, float& a3)
{
    float4 al = *(const float4*)(A_log + d * D_STATE + 4 * sg);
    a0 = -expf(al.x); a1 = -expf(al.y); a2 = -expf(al.z); a3 = -expf(al.w);
    float n0 = (float)(4 * sg + 1);
    bool ok = fabsf(a0 + n0)       < 1e-3f * n0 &&
              fabsf(a1 + (n0+1))  < 1e-3f * (n0+1) &&
              fabsf(a2 + (n0+2))  < 1e-3f * (n0+2) &&
              fabsf(a3 + (n0+3))  < 1e-3f * (n0+3);
    return __all_sync(0xffffffffu, ok);
}

template<bool FAST>
__device__ __forceinline__ void p1_body(
    const float* pdt, const float* pxc, const float* pbc,
    int sg, float a0, float a1, float a2, float a3,
    float4& hout, float4& pout)
{
    float h0=0.f,h1=0.f,h2=0.f,h3=0.f;
    float P0=1.f,P1=1.f,P2=1.f,P3=1.f;
    float dbuf[4], xbuf[4]; float4 Bbuf[4];
#pragma unroll
    for (int j = 0; j < 4; j++) {
        dbuf[j] = pdt[(size_t)j * D_INNER];
        xbuf[j] = pxc[(size_t)j * D_INNER];
        Bbuf[j] = *(const float4*)(pbc + (size_t)j * 48);
    }
    for (int t = 0; t < CH; t += 4) {
#pragma unroll
        for (int j = 0; j < 4; j++) {
            float dtv = dbuf[j], xcv = xbuf[j]; float4 B = Bbuf[j];
            int tn = t + 4 + j; if (tn > CH - 1) tn = CH - 1;
            dbuf[j] = pdt[(size_t)tn * D_INNER];
            xbuf[j] = pxc[(size_t)tn * D_INNER];
            Bbuf[j] = *(const float4*)(pbc + (size_t)tn * 48);
            float u = dtv * xcv;
            float e0,e1,e2,e3;
            exp_powers(FAST, dtv, sg, a0,a1,a2,a3, e0,e1,e2,e3);
            h0 = fmaf(h0, e0, u * B.x);  P0 *= e0;
            h1 = fmaf(h1, e1, u * B.y);  P1 *= e1;
            h2 = fmaf(h2, e2, u * B.z);  P2 *= e2;
            h3 = fmaf(h3, e3, u * B.w);  P3 *= e3;
        }
    }
    hout = make_float4(h0,h1,h2,h3);
    pout = make_float4(P0,P1,P2,P3);
}

__global__ void scan_p1(const float* __restrict__ dt, const float* __restrict__ xc,
                        const float* __restrict__ dbl, const float* __restrict__ A_log,
                        float* __restrict__ hend, float* __restrict__ pend)
{
    int warp = (blockIdx.x * blockDim.x + threadIdx.x) >> 5;
    int lane = threadIdx.x & 31;
    int b = warp >> 10;
    int rem = warp & 1023;
    int dgrp = rem >> 4;
    int chunk = rem & 15;
    int dl = lane >> 2, sg = lane & 3;
    int d = dgrp * 8 + dl;
    int t0 = chunk * CH;

    const float* pdt = dt  + ((size_t)b * SEQ + t0) * D_INNER + d;
    const float* pxc = xc  + ((size_t)b * SEQ + t0) * D_INNER + d;
    const float* pbc = dbl + ((size_t)b * SEQ + t0) * 48 + DT_RANK + 4 * sg;

    float a0,a1,a2,a3;
    bool fast = fast_check(A_log, d, sg, a0,a1,a2,a3);

    float4 ho, po;
    if (fast) p1_body<true >(pdt, pxc, pbc, sg, a0,a1,a2,a3, ho, po);
    else      p1_body<false>(pdt, pxc, pbc, sg, a0,a1,a2,a3, ho, po);

    size_t base = ((size_t)(b * NCH + chunk) * D_INNER + d) * D_STATE + 4 * sg;
    *(float4*)(hend + base) = ho;
    *(float4*)(pend + base) = po;
}

__global__ void scan_comb(const float* __restrict__ hend, const float* __restrict__ pend,
                          float* __restrict__ carry)
{
    int idx = blockIdx.x * blockDim.x + threadIdx.x;   // 65536
    int b = idx >> 13;
    int r = idx & 8191;
    float c = 0.f;
    carry[(size_t)(b * NCH) * 8192 + r] = 0.f;
    for (int ch = 1; ch < NCH; ch++) {
        size_t prev = (size_t)(b * NCH + ch - 1) * 8192 + r;
        c = fmaf(pend[prev], c, hend[prev]);
        carry[(size_t)(b * NCH + ch) * 8192 + r] = c;
    }
}

template<bool FAST>
__device__ __forceinline__ void p2_body(
    const float* pdt, const float* pxc, const float* pz, const float* pbc,
    float* py, int sg, float a0, float a1, float a2, float a3, float Dd, float4 hin)
{
    float h0=hin.x, h1=hin.y, h2=hin.z, h3=hin.w;
    float dbuf[4], xbuf[4], zbuf[4]; float4 Bbuf[4], Cbuf[4];
#pragma unroll
    for (int j = 0; j < 4; j++) {
        dbuf[j] = pdt[(size_t)j * D_INNER];
        xbuf[j] = pxc[(size_t)j * D_INNER];
        zbuf[j] = pz [(size_t)j * (2*D_INNER)];
        Bbuf[j] = *(const float4*)(pbc + (size_t)j * 48);
        Cbuf[j] = *(const float4*)(pbc + (size_t)j * 48 + D_STATE);
    }
    for (int t = 0; t < CH; t += 4) {
        float yp[4], xs[4], zs[4];
#pragma unroll
        for (int j = 0; j < 4; j++) {
            float dtv = dbuf[j], xcv = xbuf[j], zv = zbuf[j];
            float4 B = Bbuf[j], Cv = Cbuf[j];
            int tn = t + 4 + j; if (tn > CH - 1) tn = CH - 1;
            dbuf[j] = pdt[(size_t)tn * D_INNER];
            xbuf[j] = pxc[(size_t)tn * D_INNER];
            zbuf[j] = pz [(size_t)tn * (2*D_INNER)];
            Bbuf[j] = *(const float4*)(pbc + (size_t)tn * 48);
            Cbuf[j] = *(const float4*)(pbc + (size_t)tn * 48 + D_STATE);
            float u = dtv * xcv;
            float e0,e1,e2,e3;
            exp_powers(FAST, dtv, sg, a0,a1,a2,a3, e0,e1,e2,e3);
            h0 = fmaf(h0, e0, u * B.x);
            h1 = fmaf(h1, e1, u * B.y);
            h2 = fmaf(h2, e2, u * B.z);
            h3 = fmaf(h3, e3, u * B.w);
            float y = h0 * Cv.x;
            y = fmaf(h1, Cv.y, y);
            y = fmaf(h2, Cv.z, y);
            y = fmaf(h3, Cv.w, y);
            yp[j] = y; xs[j] = xcv; zs[j] = zv;
        }
#pragma unroll
        for (int j = 0; j < 4; j++)
            yp[j] += __shfl_xor_sync(0xffffffffu, yp[j], 1);
#pragma unroll
        for (int j = 0; j < 4; j++)
            yp[j] += __shfl_xor_sync(0xffffffffu, yp[j], 2);
        if (sg == 0) {
#pragma unroll
            for (int j = 0; j < 4; j++) {
                float yy = fmaf(xs[j], Dd, yp[j]);
                float sz = zs[j] / (1.f + __expf(-zs[j]));
                py[(size_t)(t + j) * D_INNER] = yy * sz;
            }
        }
    }
}

__global__ void scan_p2(const float* __restrict__ dt, const float* __restrict__ xc,
                        const float* __restrict__ dbl, const float* __restrict__ xz,
                        const float* __restrict__ A_log, const float* __restrict__ Dv,
                        const float* __restrict__ carry, float* __restrict__ yb)
{
    int warp = (blockIdx.x * blockDim.x + threadIdx.x) >> 5;
    int lane = threadIdx.x & 31;
    int b = warp >> 10;
    int rem = warp & 1023;
    int dgrp = rem >> 4;
    int chunk = rem & 15;
    int dl = lane >> 2, sg = lane & 3;
    int d = dgrp * 8 + dl;
    int t0 = chunk * CH;

    const float* pdt = dt  + ((size_t)b * SEQ + t0) * D_INNER + d;
    const float* pxc = xc  + ((size_t)b * SEQ + t0) * D_INNER + d;
    const float* pz  = xz  + ((size_t)b * SEQ + t0) * (2*D_INNER) + D_INNER + d;
    const float* pbc = dbl + ((size_t)b * SEQ + t0) * 48 + DT_RANK + 4 * sg;
    float* py        = yb  + ((size_t)b * SEQ + t0) * D_INNER + d;

    float a0,a1,a2,a3;
    bool fast = fast_check(A_log, d, sg, a0,a1,a2,a3);
    float Dd = Dv[d];
    float4 hin = *(const float4*)(carry +
        ((size_t)(b * NCH + chunk) * D_INNER + d) * D_STATE + 4 * sg);

    if (fast) p2_body<true >(pdt, pxc, pz, pbc, py, sg, a0,a1,a2,a3, Dd, hin);
    else      p2_body<false>(pdt, pxc, pz, pbc, py, sg, a0,a1,a2,a3, Dd, hin);
}

// ---------------- host side ----------------
static inline void launch_gemm(const float* A, const float* W, const float* bias,
                               float* C, int M, int N, int K, int ldc, bool acc)
{
    dim3 grid((N + GBN - 1) / GBN, (M + GBM - 1) / GBM);
    size_t smem = SMEM_WORDS * sizeof(uint32_t);
    if (acc) gemm_bf16<true><<<grid, 256, smem>>>(A, W, bias, C, M, N, K, ldc);
    else     gemm_bf16<false><<<grid, 256, smem>>>(A, W, bias, C, M, N, K, ldc);
}

extern "C" void kernel_launch(void* const* d_in, const int* in_sizes, int n_in,
                              void* d_out, int out_size)
{
    const float* wav    = (const float*)d_in[0];
    const float* lib    = (const float*)d_in[1];
    const float* w2v_W  = (const float*)d_in[2];
    const float* w2v_b  = (const float*)d_in[3];
    const float* lib_W  = (const float*)d_in[4];
    const float* lib_b  = (const float*)d_in[5];
    const float* fuse_W = (const float*)d_in[6];
    const float* fuse_b = (const float*)d_in[7];
    const float* proj_W = (const float*)d_in[8];
    const float* proj_b = (const float*)d_in[9];
    const float* ln_g   = (const float*)d_in[10];
    const float* ln_b   = (const float*)d_in[11];
    const float* in_W   = (const float*)d_in[12];
    const float* conv_W = (const float*)d_in[13];
    const float* conv_b = (const float*)d_in[14];
    const float* xproj_W= (const float*)d_in[15];
    const float* dt_W   = (const float*)d_in[16];
    const float* dt_b   = (const float*)d_in[17];
    const float* A_log  = (const float*)d_in[18];
    const float* D_vec  = (const float*)d_in[19];
    const float* out_W  = (const float*)d_in[20];
    const float* fnorm_g= (const float*)d_in[21];
    const float* fnorm_b= (const float*)d_in[22];
    float* out = (float*)d_out;

    size_t smem = SMEM_WORDS * sizeof(uint32_t);
    cudaFuncSetAttribute(gemm_bf16<false>, cudaFuncAttributeMaxDynamicSharedMemorySize, (int)smem);
    cudaFuncSetAttribute(gemm_bf16<true>,  cudaFuncAttributeMaxDynamicSharedMemorySize, (int)smem);

    float *wl, *tb, *hb, *xln, *xzb, *xcb, *dblb, *dtb2, *yb, *he, *pe, *ca;
    cudaGetSymbolAddress((void**)&wl,   g_wl);
    cudaGetSymbolAddress((void**)&tb,   g_t);
    cudaGetSymbolAddress((void**)&hb,   g_h);
    cudaGetSymbolAddress((void**)&xln,  g_xln);
    cudaGetSymbolAddress((void**)&xzb,  g_xz);
    cudaGetSymbolAddress((void**)&xcb,  g_xc);
    cudaGetSymbolAddress((void**)&dblb, g_dbl);
    cudaGetSymbolAddress((void**)&dtb2, g_dt);
    cudaGetSymbolAddress((void**)&yb,   g_y);
    cudaGetSymbolAddress((void**)&he,   g_hend);
    cudaGetSymbolAddress((void**)&pe,   g_pend);
    cudaGetSymbolAddress((void**)&ca,   g_carry);

    const int M = M_ROWS;

    launch_gemm(wav, w2v_W, w2v_b, wl,           M, D_MODEL, W2V_DIM,   2*D_MODEL, false);
    launch_gemm(lib, lib_W, lib_b, wl + D_MODEL, M, D_MODEL, LIB_DIM,   2*D_MODEL, false);
    launch_gemm(wl,  fuse_W, fuse_b, tb,         M, D_MODEL, 2*D_MODEL, D_MODEL,   false);
    launch_gemm(tb,  proj_W, proj_b, hb,         M, D_MODEL, D_MODEL,   D_MODEL,   false);

    const int SCAN_BLOCKS = (BATCH * 64 * NCH) / 8;

    for (int i = 0; i < N_LAYERS; i++) {
        const float* lg  = ln_g   + i * D_MODEL;
        const float* lb  = ln_b   + i * D_MODEL;
        const float* iw  = in_W   + (size_t)i * 2*D_INNER * D_MODEL;
        const float* cw  = conv_W + (size_t)i * D_INNER * 4;
        const float* cb  = conv_b + (size_t)i * D_INNER;
        const float* xw  = xproj_W+ (size_t)i * (DT_RANK + 2*D_STATE) * D_INNER;
        const float* dw  = dt_W   + (size_t)i * D_INNER * DT_RANK;
        const float* db  = dt_b   + (size_t)i * D_INNER;
        const float* al  = A_log  + (size_t)i * D_INNER * D_STATE;
        const float* dv  = D_vec  + (size_t)i * D_INNER;
        const float* ow  = out_W  + (size_t)i * D_MODEL * D_INNER;

        ln_k<<<M_ROWS / 8, 256>>>(hb, lg, lb, xln);
        launch_gemm(xln, iw, nullptr, xzb, M, 2*D_INNER, D_MODEL, 2*D_INNER, false);
        fcx_k<<<M_ROWS, 128>>>(xzb, cw, cb, xw, dw, db, xcb, dblb, dtb2);
        scan_p1<<<SCAN_BLOCKS, 256>>>(dtb2, xcb, dblb, al, he, pe);
        scan_comb<<<64, 1024>>>(he, pe, ca);
        scan_p2<<<SCAN_BLOCKS, 256>>>(dtb2, xcb, dblb, xzb, al, dv, ca, yb);
        launch_gemm(yb, ow, nullptr, hb, M, D_MODEL, D_INNER, D_MODEL, true);
    }

    ln_k<<<M_ROWS / 8, 256>>>(hb, fnorm_g, fnorm_b, out);
}